// round 15
// baseline (speedup 1.0000x reference)
#include <cuda_runtime.h>
#include <cuda_bf16.h>
#include <math.h>
#include <stdint.h>

#define DD 1024
#define HEADS 16
#define DH 64
#define B_LAT 9
#define B_X 8
#define N_KV 256
#define N_Q 64
#define KV_PER_B (N_KV + N_Q)       /* 320  */
#define ROWS_X (B_X * N_KV)         /* 2048 */
#define ROWS_LAT (B_LAT * N_Q)      /* 576  */
#define ROWS_KV (B_X * KV_PER_B)    /* 2560 */
#define EPS 1e-5f
#define NSUB 40                     /* 2560/64 key subtiles */
#define NPART40 (B_LAT * HEADS * NSUB)   /* 5760 */
#define K3 3072                     /* split-bf16 extended K = 3*1024 */

// ---------------- scratch (static device globals; no allocation) ----------------
__device__ float g_q [ROWS_LAT * DD];        // split-K half 0, then reduced sum
__device__ float g_q2[ROWS_LAT * DD];        // split-K half 1
__device__ float g_kv [ROWS_KV * 2 * DD];
__device__ float g_kv2[ROWS_KV * 2 * DD];
__device__ float g_pO[(size_t)NPART40 * 64 * 64];   /* 94.4 MB */
__device__ float g_pm[NPART40 * 64];
__device__ float g_pl[NPART40 * 64];
// split-bf16 operands: A3 = [Ah | Ah | Al] rows [M,3072]; W3 = [Wh | Wl | Wh] rows [N,3072]
__device__ __nv_bfloat16 g_a3kv[(size_t)ROWS_KV * K3];
__device__ __nv_bfloat16 g_a3small[(size_t)ROWS_LAT * K3];   // lnlat splits, later ao splits
__device__ __nv_bfloat16 g_w3q[(size_t)DD * K3];
__device__ __nv_bfloat16 g_w3kv[(size_t)(2 * DD) * K3];
__device__ __nv_bfloat16 g_w3out[(size_t)DD * K3];

// ---------------- PTX helpers (base ISA only: sm_80-compatible) ----------------
__device__ __forceinline__ uint32_t smem_u32(const void* p) {
    uint32_t a;
    asm("{ .reg .u64 t; cvta.to.shared.u64 t, %1; cvt.u32.u64 %0, t; }" : "=r"(a) : "l"(p));
    return a;
}
__device__ __forceinline__ void cp_async16(uint32_t s, const void* g, int sz) {
    asm volatile("cp.async.cg.shared.global [%0], [%1], 16, %2;"
                 :: "r"(s), "l"(g), "r"(sz) : "memory");
}
#define CP_COMMIT()  asm volatile("cp.async.commit_group;" ::: "memory")
#define CP_WAIT0()   asm volatile("cp.async.wait_group 0;" ::: "memory")

__device__ __forceinline__ void ldm_x4(uint32_t* r, uint32_t a) {
    asm volatile("ldmatrix.sync.aligned.m8n8.x4.shared.b16 {%0,%1,%2,%3}, [%4];"
                 : "=r"(r[0]), "=r"(r[1]), "=r"(r[2]), "=r"(r[3]) : "r"(a));
}
__device__ __forceinline__ void mma_bf16(float* d, const uint32_t* a, uint32_t b0, uint32_t b1) {
    asm volatile("mma.sync.aligned.m16n8k16.row.col.f32.bf16.bf16.f32 "
                 "{%0,%1,%2,%3}, {%4,%5,%6,%7}, {%8,%9}, {%0,%1,%2,%3};"
                 : "+f"(d[0]), "+f"(d[1]), "+f"(d[2]), "+f"(d[3])
                 : "r"(a[0]), "r"(a[1]), "r"(a[2]), "r"(a[3]), "r"(b0), "r"(b1));
}

// store 4 fp32 values as split-bf16 triple at dst[0], dst[1024], dst[2048] (8B stores)
__device__ __forceinline__ void store_split4_A(__nv_bfloat16* dst, float4 v) {
    __nv_bfloat162 H0 = {__float2bfloat16(v.x), __float2bfloat16(v.y)};
    __nv_bfloat162 H1 = {__float2bfloat16(v.z), __float2bfloat16(v.w)};
    __nv_bfloat162 L0 = {__float2bfloat16(v.x - __bfloat162float(H0.x)),
                         __float2bfloat16(v.y - __bfloat162float(H0.y))};
    __nv_bfloat162 L1 = {__float2bfloat16(v.z - __bfloat162float(H1.x)),
                         __float2bfloat16(v.w - __bfloat162float(H1.y))};
    uint2 H = make_uint2(*(uint32_t*)&H0, *(uint32_t*)&H1);
    uint2 L = make_uint2(*(uint32_t*)&L0, *(uint32_t*)&L1);
    *(uint2*)&dst[0]    = H;
    *(uint2*)&dst[1024] = H;
    *(uint2*)&dst[2048] = L;
}

// ---------------- merged LN + weight conversion (one launch, 256 threads) ----------------
#define LN_BLKS (ROWS_X + ROWS_LAT)   /* 2624 */
__global__ void ln_convW(const float* __restrict__ x, const float* __restrict__ lat,
                         const float* __restrict__ g1, const float* __restrict__ b1,
                         const float* __restrict__ g2, const float* __restrict__ b2,
                         const float* __restrict__ Wq, const float* __restrict__ Wkv,
                         const float* __restrict__ Wout) {
    __shared__ float shmem[32 * 33];
    int tid = threadIdx.x;
    int blk = blockIdx.x;

    if (blk < LN_BLKS) {
        int row = blk;
        const float *src, *g, *b;
        __nv_bfloat16 *dst0, *dst1 = nullptr;
        if (row < ROWS_X) {
            int bb = row / N_KV, n = row % N_KV;
            src = x + (size_t)row * DD; g = g1; b = b1;
            dst0 = g_a3kv + (size_t)(bb * KV_PER_B + n) * K3;
        } else {
            int lr = row - ROWS_X;
            int bb = lr / N_Q, n = lr % N_Q;
            src = lat + (size_t)lr * DD; g = g2; b = b2;
            dst0 = g_a3small + (size_t)lr * K3;
            if (bb < B_X) dst1 = g_a3kv + (size_t)(bb * KV_PER_B + N_KV + n) * K3;
        }
        float4 v = ((const float4*)src)[tid];
        float s  = v.x + v.y + v.z + v.w;
        float ss = v.x*v.x + v.y*v.y + v.z*v.z + v.w*v.w;
        #pragma unroll
        for (int o = 16; o; o >>= 1) {
            s  += __shfl_xor_sync(0xFFFFFFFFu, s,  o);
            ss += __shfl_xor_sync(0xFFFFFFFFu, ss, o);
        }
        float* sb  = shmem;
        float* ssb = shmem + 8;
        int wid = tid >> 5, lane = tid & 31;
        if (lane == 0) { sb[wid] = s; ssb[wid] = ss; }
        __syncthreads();
        float ts = 0.f, tss = 0.f;
        #pragma unroll
        for (int i = 0; i < 8; i++) { ts += sb[i]; tss += ssb[i]; }
        float mean = ts * (1.0f / DD);
        float var  = tss * (1.0f / DD) - mean * mean;
        float inv  = rsqrtf(var + EPS);
        float4 gg = ((const float4*)g)[tid];
        float4 bb4 = ((const float4*)b)[tid];
        float4 o;
        o.x = (v.x - mean) * inv * gg.x + bb4.x;
        o.y = (v.y - mean) * inv * gg.y + bb4.y;
        o.z = (v.z - mean) * inv * gg.z + bb4.z;
        o.w = (v.w - mean) * inv * gg.w + bb4.w;
        store_split4_A(dst0 + tid * 4, o);
        if (dst1) store_split4_A(dst1 + tid * 4, o);
    } else {
        int t = blk - LN_BLKS;
        const float* W; __nv_bfloat16* dst; int N; int lt;
        if (t < 1024)      { W = Wq;   dst = g_w3q;   N = DD;     lt = t; }
        else if (t < 3072) { W = Wkv;  dst = g_w3kv;  N = 2 * DD; lt = t - 1024; }
        else               { W = Wout; dst = g_w3out; N = DD;     lt = t - 3072; }
        int ntiles_x = N / 32;
        int n0 = (lt % ntiles_x) * 32, k0 = (lt / ntiles_x) * 32;
        float (*tt)[33] = (float(*)[33])shmem;
        int tx = tid & 31, ty = tid >> 5;
        #pragma unroll
        for (int j = 0; j < 4; j++)
            tt[ty + j * 8][tx] = W[(size_t)(k0 + ty + j * 8) * N + n0 + tx];
        __syncthreads();
        #pragma unroll
        for (int j = 0; j < 4; j++) {
            int n = n0 + ty + j * 8, k = k0 + tx;
            float a = tt[tx][ty + j * 8];
            __nv_bfloat16 h = __float2bfloat16(a);
            __nv_bfloat16 l = __float2bfloat16(a - __bfloat162float(h));
            size_t o = (size_t)n * K3 + k;
            dst[o] = h; dst[o + 1024] = l; dst[o + 2048] = h;
        }
    }
}

// ---------------- mma.sync bf16 GEMM core (2-stage, 128-row tiles, K-range param) ----------------
#define GBK 64
#define KST 72
#define ABUF (128 * KST * 2)
#define STAGE (2 * ABUF)
#define GEMM_SMEM (2 * STAGE)                /* 73728 B */
#define NCH (K3 / GBK)                       /* 48 */

__device__ __forceinline__ void gemm_core(const __nv_bfloat16* __restrict__ A3,
                                          const __nv_bfloat16* __restrict__ B3,
                                          float* __restrict__ C,
                                          int M, int N, int br, int bc,
                                          int kb0, int kbn,
                                          unsigned char* dynsm) {
    int tid = threadIdx.x, wid = tid >> 5, lane = tid & 31;
    int wm = (wid >> 2) * 64;
    int wn = (wid & 3) * 32;

    auto issue = [&](int kb, int buf) {
        unsigned char* sb = dynsm + buf * STAGE;
        const __nv_bfloat16* Ab = A3 + kb * GBK;
        const __nv_bfloat16* Bb = B3 + (size_t)bc * K3 + kb * GBK;
        #pragma unroll
        for (int j = 0; j < 4; j++) {
            int idx = tid + j * 256;
            int r = idx >> 3, c8 = idx & 7;
            int gr = br + r; int sz = (gr < M) ? 16 : 0;
            if (gr >= M) gr = M - 1;
            cp_async16(smem_u32(sb + (r * KST + c8 * 8) * 2),
                       Ab + (size_t)gr * K3 + c8 * 8, sz);
            cp_async16(smem_u32(sb + ABUF + (r * KST + c8 * 8) * 2),
                       Bb + (size_t)r * K3 + c8 * 8, 16);
        }
        CP_COMMIT();
    };

    float acc[4][4][4] = {};

    issue(kb0, 0);
    CP_WAIT0();
    __syncthreads();

    for (int k = 0; k < kbn; k++) {
        int cur = k & 1;
        if (k + 1 < kbn) issue(kb0 + k + 1, cur ^ 1);

        const unsigned char* sA = dynsm + cur * STAGE;
        const unsigned char* sB = sA + ABUF;
        #pragma unroll
        for (int ks = 0; ks < 4; ks++) {
            int k0 = ks * 16;
            uint32_t a[4][4];
            #pragma unroll
            for (int mt = 0; mt < 4; mt++) {
                int arow = wm + mt * 16 + (lane & 15);
                int acol = k0 + (lane >> 4) * 8;
                ldm_x4(a[mt], smem_u32(sA + (arow * KST + acol) * 2));
            }
            uint32_t b[2][4];
            #pragma unroll
            for (int np = 0; np < 2; np++) {
                int nrow = wn + np * 16 + (lane & 7) + ((lane >> 4) << 3);
                int kcol = k0 + ((lane >> 3) & 1) * 8;
                ldm_x4(b[np], smem_u32(sB + (nrow * KST + kcol) * 2));
            }
            #pragma unroll
            for (int mt = 0; mt < 4; mt++)
                #pragma unroll
                for (int nt = 0; nt < 4; nt++)
                    mma_bf16(acc[mt][nt], a[mt], b[nt >> 1][(nt & 1) * 2],
                             b[nt >> 1][(nt & 1) * 2 + 1]);
        }
        if (k + 1 < kbn) CP_WAIT0();
        __syncthreads();
    }

    #pragma unroll
    for (int mt = 0; mt < 4; mt++) {
        int r0 = br + wm + mt * 16 + (lane >> 2);
        #pragma unroll
        for (int nt = 0; nt < 4; nt++) {
            int c = bc + wn + nt * 8 + (lane & 3) * 2;
            if (r0 < M)
                *(float2*)&C[(size_t)r0 * N + c] = make_float2(acc[mt][nt][0], acc[mt][nt][1]);
            if (r0 + 8 < M)
                *(float2*)&C[(size_t)(r0 + 8) * N + c] = make_float2(acc[mt][nt][2], acc[mt][nt][3]);
        }
    }
}

// ---------------- 64-row-tile GEMM core (output projection, full K) ----------------
#define ABUF64 (64 * KST * 2)
#define STAGE64 (ABUF64 + ABUF)
#define GEMM64_SMEM (2 * STAGE64)            /* 55296 B */

__device__ __forceinline__ void gemm_core64(const __nv_bfloat16* __restrict__ A3,
                                            const __nv_bfloat16* __restrict__ B3,
                                            float* __restrict__ C,
                                            int M, int N, int br, int bc,
                                            unsigned char* dynsm) {
    int tid = threadIdx.x, wid = tid >> 5, lane = tid & 31;
    int wm = (wid >> 2) * 32;
    int wn = (wid & 3) * 32;

    auto issue = [&](int kb, int buf) {
        unsigned char* sb = dynsm + buf * STAGE64;
        const __nv_bfloat16* Ab = A3 + kb * GBK;
        const __nv_bfloat16* Bb = B3 + (size_t)bc * K3 + kb * GBK;
        #pragma unroll
        for (int j = 0; j < 2; j++) {
            int idx = tid + j * 256;
            int r = idx >> 3, c8 = idx & 7;
            int gr = br + r; int sz = (gr < M) ? 16 : 0;
            if (gr >= M) gr = M - 1;
            cp_async16(smem_u32(sb + (r * KST + c8 * 8) * 2),
                       Ab + (size_t)gr * K3 + c8 * 8, sz);
        }
        #pragma unroll
        for (int j = 0; j < 4; j++) {
            int idx = tid + j * 256;
            int r = idx >> 3, c8 = idx & 7;
            cp_async16(smem_u32(sb + ABUF64 + (r * KST + c8 * 8) * 2),
                       Bb + (size_t)r * K3 + c8 * 8, 16);
        }
        CP_COMMIT();
    };

    float acc[2][4][4] = {};

    issue(0, 0);
    CP_WAIT0();
    __syncthreads();

    for (int kb = 0; kb < NCH; kb++) {
        int cur = kb & 1;
        if (kb + 1 < NCH) issue(kb + 1, cur ^ 1);

        const unsigned char* sA = dynsm + cur * STAGE64;
        const unsigned char* sB = sA + ABUF64;
        #pragma unroll
        for (int ks = 0; ks < 4; ks++) {
            int k0 = ks * 16;
            uint32_t a[2][4];
            #pragma unroll
            for (int mt = 0; mt < 2; mt++) {
                int arow = wm + mt * 16 + (lane & 15);
                int acol = k0 + (lane >> 4) * 8;
                ldm_x4(a[mt], smem_u32(sA + (arow * KST + acol) * 2));
            }
            uint32_t b[2][4];
            #pragma unroll
            for (int np = 0; np < 2; np++) {
                int nrow = wn + np * 16 + (lane & 7) + ((lane >> 4) << 3);
                int kcol = k0 + ((lane >> 3) & 1) * 8;
                ldm_x4(b[np], smem_u32(sB + (nrow * KST + kcol) * 2));
            }
            #pragma unroll
            for (int mt = 0; mt < 2; mt++)
                #pragma unroll
                for (int nt = 0; nt < 4; nt++)
                    mma_bf16(acc[mt][nt], a[mt], b[nt >> 1][(nt & 1) * 2],
                             b[nt >> 1][(nt & 1) * 2 + 1]);
        }
        if (kb + 1 < NCH) CP_WAIT0();
        __syncthreads();
    }

    #pragma unroll
    for (int mt = 0; mt < 2; mt++) {
        int r0 = br + wm + mt * 16 + (lane >> 2);
        #pragma unroll
        for (int nt = 0; nt < 4; nt++) {
            int c = bc + wn + nt * 8 + (lane & 3) * 2;
            if (r0 < M)
                *(float2*)&C[(size_t)r0 * N + c] = make_float2(acc[mt][nt][0], acc[mt][nt][1]);
            if (r0 + 8 < M)
                *(float2*)&C[(size_t)(r0 + 8) * N + c] = make_float2(acc[mt][nt][2], acc[mt][nt][3]);
        }
    }
}

// merged Q + KV projection with split-K=2: 720 CTAs
// bid < 360: K chunks [0,24) -> g_q / g_kv ; bid >= 360: chunks [24,48) -> g_q2 / g_kv2
#define KV_TILES 320
#define Q_TILES  40
#define TILES_HALF (KV_TILES + Q_TILES)   /* 360 */

__global__ __launch_bounds__(256)
void gemm_qkv() {
    extern __shared__ __align__(16) unsigned char dynsm[];
    int bid = blockIdx.x;
    int split = (bid >= TILES_HALF) ? 1 : 0;
    int t = bid - split * TILES_HALF;
    int kb0 = split * (NCH / 2);
    if (t < KV_TILES) {
        int bx = t & 15, by = t >> 4;
        gemm_core(g_a3kv, g_w3kv, split ? g_kv2 : g_kv, ROWS_KV, 2 * DD,
                  by * 128, bx * 128, kb0, NCH / 2, dynsm);
    } else {
        int u = t - KV_TILES;
        int bx = u & 7, by = u >> 3;
        gemm_core(g_a3small, g_w3q, split ? g_q2 : g_q, ROWS_LAT, DD,
                  by * 128, bx * 128, kb0, NCH / 2, dynsm);
    }
}

// deterministic fold of split-K halves: g_q += g_q2, g_kv += g_kv2 (float4 grid-stride)
#define QN4 (ROWS_LAT * DD / 4)              /* 147456  */
#define KVN4 (ROWS_KV * 2 * DD / 4)          /* 1310720 */
__global__ __launch_bounds__(256)
void reduce_halves() {
    int stride = gridDim.x * 256;
    for (int i = blockIdx.x * 256 + threadIdx.x; i < QN4 + KVN4; i += stride) {
        if (i < QN4) {
            float4 a = ((const float4*)g_q)[i];
            float4 b = ((const float4*)g_q2)[i];
            ((float4*)g_q)[i] = make_float4(a.x + b.x, a.y + b.y, a.z + b.z, a.w + b.w);
        } else {
            int j = i - QN4;
            float4 a = ((const float4*)g_kv)[j];
            float4 b = ((const float4*)g_kv2)[j];
            ((float4*)g_kv)[j] = make_float4(a.x + b.x, a.y + b.y, a.z + b.z, a.w + b.w);
        }
    }
}

__global__ __launch_bounds__(256)
void gemm_out(float* __restrict__ C) {
    extern __shared__ __align__(16) unsigned char dynsm[];
    gemm_core64(g_a3small, g_w3out, C, ROWS_LAT, DD, blockIdx.y * 64, blockIdx.x * 128, dynsm);
}

// ---------------- attention: one block per 64-key subtile, single-pass softmax ----------------
// (verbatim R12 version; reads the reduced g_q / g_kv)
#define ASTR 68

__global__ __launch_bounds__(256)
void attn_part(const int* __restrict__ um_p) {
    int s  = blockIdx.x;
    int h  = blockIdx.y;
    int qb = blockIdx.z;
    int um = *um_p;
    bool masked = (um != 0) && (qb < B_X);
    if (masked && s >= 5) return;   // whole block exits before any barrier
    int kbase = masked ? (qb * KV_PER_B + s * 64) : (s * 64);

    extern __shared__ float smf[];
    float* Qs = smf;                    // [d][q] pre-scaled
    float* Ks = smf + 64 * ASTR;        // [d][k]
    float* Vs = smf + 2 * 64 * ASTR;    // [k][d]
    float* Ps = smf + 3 * 64 * ASTR;    // [q][k]
    float* mrow = smf + 4 * 64 * ASTR;  // [64]
    float* lrow = mrow + 64;

    int tid = threadIdx.x;
    int ty = tid >> 4, tx = tid & 15;

    #pragma unroll
    for (int it = 0; it < 4; it++) {
        int row = ty + it * 16;
        int col = tx * 4;
        float4 v = *(const float4*)&g_q[(size_t)(qb * 64 + row) * DD + h * DH + col];
        Qs[(col + 0) * ASTR + row] = v.x * 0.125f;
        Qs[(col + 1) * ASTR + row] = v.y * 0.125f;
        Qs[(col + 2) * ASTR + row] = v.z * 0.125f;
        Qs[(col + 3) * ASTR + row] = v.w * 0.125f;
        const float* base = g_kv + (size_t)(kbase + row) * (2 * DD) + h * DH + col;
        float4 kk = *(const float4*)base;
        Ks[(col + 0) * ASTR + row] = kk.x;
        Ks[(col + 1) * ASTR + row] = kk.y;
        Ks[(col + 2) * ASTR + row] = kk.z;
        Ks[(col + 3) * ASTR + row] = kk.w;
        *(float4*)&Vs[row * ASTR + col] = *(const float4*)(base + DD);
    }
    __syncthreads();

    float sacc[4][4] = {};
    #pragma unroll
    for (int d = 0; d < 64; d++) {
        float4 aq = *(const float4*)&Qs[d * ASTR + ty * 4];
        float4 bk = *(const float4*)&Ks[d * ASTR + tx * 4];
        sacc[0][0] += aq.x * bk.x; sacc[0][1] += aq.x * bk.y;
        sacc[0][2] += aq.x * bk.z; sacc[0][3] += aq.x * bk.w;
        sacc[1][0] += aq.y * bk.x; sacc[1][1] += aq.y * bk.y;
        sacc[1][2] += aq.y * bk.z; sacc[1][3] += aq.y * bk.w;
        sacc[2][0] += aq.z * bk.x; sacc[2][1] += aq.z * bk.y;
        sacc[2][2] += aq.z * bk.z; sacc[2][3] += aq.z * bk.w;
        sacc[3][0] += aq.w * bk.x; sacc[3][1] += aq.w * bk.y;
        sacc[3][2] += aq.w * bk.z; sacc[3][3] += aq.w * bk.w;
    }
    #pragma unroll
    for (int i = 0; i < 4; i++)
        #pragma unroll
        for (int j = 0; j < 4; j++)
            Ps[(ty * 4 + i) * ASTR + tx * 4 + j] = sacc[i][j];
    __syncthreads();

    {
        int r = tid >> 2, part = tid & 3;
        float rm = -INFINITY;
        #pragma unroll
        for (int i = 0; i < 16; i++)
            rm = fmaxf(rm, Ps[r * ASTR + part * 16 + i]);
        rm = fmaxf(rm, __shfl_xor_sync(0xFFFFFFFFu, rm, 1));
        rm = fmaxf(rm, __shfl_xor_sync(0xFFFFFFFFu, rm, 2));
        float psum = 0.f;
        #pragma unroll
        for (int i = 0; i < 16; i++) {
            float p = __expf(Ps[r * ASTR + part * 16 + i] - rm);
            Ps[r * ASTR + part * 16 + i] = p;
            psum += p;
        }
        psum += __shfl_xor_sync(0xFFFFFFFFu, psum, 1);
        psum += __shfl_xor_sync(0xFFFFFFFFu, psum, 2);
        if (part == 0) { mrow[r] = rm; lrow[r] = psum; }
    }
    __syncthreads();

    float oacc[4][4] = {};
    #pragma unroll
    for (int k = 0; k < 64; k++) {
        float4 v4 = *(const float4*)&Vs[k * ASTR + tx * 4];
        float p0 = Ps[(ty * 4 + 0) * ASTR + k];
        float p1 = Ps[(ty * 4 + 1) * ASTR + k];
        float p2 = Ps[(ty * 4 + 2) * ASTR + k];
        float p3 = Ps[(ty * 4 + 3) * ASTR + k];
        oacc[0][0] += p0 * v4.x; oacc[0][1] += p0 * v4.y;
        oacc[0][2] += p0 * v4.z; oacc[0][3] += p0 * v4.w;
        oacc[1][0] += p1 * v4.x; oacc[1][1] += p1 * v4.y;
        oacc[1][2] += p1 * v4.z; oacc[1][3] += p1 * v4.w;
        oacc[2][0] += p2 * v4.x; oacc[2][1] += p2 * v4.y;
        oacc[2][2] += p2 * v4.z; oacc[2][3] += p2 * v4.w;
        oacc[3][0] += p3 * v4.x; oacc[3][1] += p3 * v4.y;
        oacc[3][2] += p3 * v4.z; oacc[3][3] += p3 * v4.w;
    }

    int pidx = (qb * HEADS + h) * NSUB + s;
    #pragma unroll
    for (int i = 0; i < 4; i++) {
        float4 o = make_float4(oacc[i][0], oacc[i][1], oacc[i][2], oacc[i][3]);
        *(float4*)&g_pO[((size_t)pidx * 64 + ty * 4 + i) * 64 + tx * 4] = o;
    }
    if (tid < 64) {
        g_pm[pidx * 64 + tid] = mrow[tid];
        g_pl[pidx * 64 + tid] = lrow[tid];
    }
}

// merge partials per (q,h) row: 5 (masked, qb<8) or 40 (dense); streaming
__global__ __launch_bounds__(256)
void attn_combine(const int* __restrict__ um_p) {
    int q = blockIdx.x * 4 + (threadIdx.x >> 6);
    int h = blockIdx.y;
    int qb = q >> 6, qq = q & 63;
    int um = *um_p;
    bool masked = (um != 0) && (qb < B_X);
    int ns = masked ? 5 : NSUB;
    int d = threadIdx.x & 63;
    int pbase = (qb * HEADS + h) * NSUB;

    float M = -INFINITY;
    for (int c = 0; c < ns; c++)
        M = fmaxf(M, g_pm[(pbase + c) * 64 + qq]);
    float L = 0.f, o = 0.f;
    for (int c = 0; c < ns; c++) {
        float e = __expf(g_pm[(pbase + c) * 64 + qq] - M);
        L += g_pl[(pbase + c) * 64 + qq] * e;
        o += g_pO[((size_t)(pbase + c) * 64 + qq) * 64 + d] * e;
    }
    float r = o / L;
    __nv_bfloat16 hh = __float2bfloat16(r);
    __nv_bfloat16 ll = __float2bfloat16(r - __bfloat162float(hh));
    __nv_bfloat16* dst = g_a3small + (size_t)q * K3 + h * DH + d;
    dst[0] = hh; dst[1024] = hh; dst[2048] = ll;
}

// ---------------- launch ----------------
#define ATTN_SMEM ((4 * 64 * ASTR + 192) * (int)sizeof(float))   /* 70400 B */

extern "C" void kernel_launch(void* const* d_in, const int* in_sizes, int n_in,
                              void* d_out, int out_size) {
    const float* x    = (const float*)d_in[0];
    const float* lat  = (const float*)d_in[1];
    const float* g1   = (const float*)d_in[2];
    const float* b1   = (const float*)d_in[3];
    const float* g2   = (const float*)d_in[4];
    const float* b2   = (const float*)d_in[5];
    const float* Wq   = (const float*)d_in[6];
    const float* Wkv  = (const float*)d_in[7];
    const float* Wout = (const float*)d_in[8];
    const int*   um   = (const int*)d_in[9];
    float* out = (float*)d_out;

    cudaFuncSetAttribute(gemm_qkv,  cudaFuncAttributeMaxDynamicSharedMemorySize, GEMM_SMEM);
    cudaFuncSetAttribute(gemm_out,  cudaFuncAttributeMaxDynamicSharedMemorySize, GEMM64_SMEM);
    cudaFuncSetAttribute(attn_part, cudaFuncAttributeMaxDynamicSharedMemorySize, ATTN_SMEM);

    // 1. LayerNorm + all weight conversions in ONE launch
    ln_convW<<<LN_BLKS + 4096, 256>>>(x, lat, g1, b1, g2, b2, Wq, Wkv, Wout);

    // 2. Q + KV projections, split-K=2 (720 CTAs), then deterministic fold
    gemm_qkv<<<2 * TILES_HALF, 256, GEMM_SMEM>>>();
    reduce_halves<<<1184, 256>>>();

    // 3. attention partials (R12-proven kernel) + streaming combine
    attn_part<<<dim3(NSUB, HEADS, B_LAT), 256, ATTN_SMEM>>>(um);
    attn_combine<<<dim3(ROWS_LAT / 4, HEADS), 256>>>(um);

    // 4. output projection (64-row tiles, 72 CTAs)
    gemm_out<<<dim3(DD / 128, ROWS_LAT / 64), 256, GEMM64_SMEM>>>(out);
}

// round 16
// speedup vs baseline: 1.0738x; 1.0738x over previous
#include <cuda_runtime.h>
#include <cuda_bf16.h>
#include <math.h>
#include <stdint.h>

#define DD 1024
#define HEADS 16
#define DH 64
#define B_LAT 9
#define B_X 8
#define N_KV 256
#define N_Q 64
#define KV_PER_B (N_KV + N_Q)       /* 320  */
#define ROWS_X (B_X * N_KV)         /* 2048 */
#define ROWS_LAT (B_LAT * N_Q)      /* 576  */
#define ROWS_KV (B_X * KV_PER_B)    /* 2560 */
#define EPS 1e-5f
#define NSUB 40                     /* 2560/64 key subtiles */
#define NPART40 (B_LAT * HEADS * NSUB)   /* 5760 */
#define K3 3072                     /* split-bf16 extended K = 3*1024 */

// ---------------- scratch (static device globals; no allocation) ----------------
__device__ float g_q[ROWS_LAT * DD];
__device__ float g_kv[ROWS_KV * 2 * DD];
__device__ float g_pO[(size_t)NPART40 * 64 * 64];   /* 94.4 MB */
__device__ float g_pm[NPART40 * 64];
__device__ float g_pl[NPART40 * 64];
// split-bf16 operands: A3 = [Ah | Ah | Al] rows [M,3072]; W3 = [Wh | Wl | Wh] rows [N,3072]
__device__ __nv_bfloat16 g_a3kv[(size_t)ROWS_KV * K3];
__device__ __nv_bfloat16 g_a3small[(size_t)ROWS_LAT * K3];   // lnlat splits, later ao splits
__device__ __nv_bfloat16 g_w3q[(size_t)DD * K3];
__device__ __nv_bfloat16 g_w3kv[(size_t)(2 * DD) * K3];
__device__ __nv_bfloat16 g_w3out[(size_t)DD * K3];

// ---------------- PTX helpers (base ISA only: sm_80-compatible) ----------------
__device__ __forceinline__ uint32_t smem_u32(const void* p) {
    uint32_t a;
    asm("{ .reg .u64 t; cvta.to.shared.u64 t, %1; cvt.u32.u64 %0, t; }" : "=r"(a) : "l"(p));
    return a;
}
__device__ __forceinline__ void cp_async16(uint32_t s, const void* g, int sz) {
    asm volatile("cp.async.cg.shared.global [%0], [%1], 16, %2;"
                 :: "r"(s), "l"(g), "r"(sz) : "memory");
}
#define CP_COMMIT()  asm volatile("cp.async.commit_group;" ::: "memory")
#define CP_WAIT0()   asm volatile("cp.async.wait_group 0;" ::: "memory")

__device__ __forceinline__ void ldm_x4(uint32_t* r, uint32_t a) {
    asm volatile("ldmatrix.sync.aligned.m8n8.x4.shared.b16 {%0,%1,%2,%3}, [%4];"
                 : "=r"(r[0]), "=r"(r[1]), "=r"(r[2]), "=r"(r[3]) : "r"(a));
}
__device__ __forceinline__ void mma_bf16(float* d, const uint32_t* a, uint32_t b0, uint32_t b1) {
    asm volatile("mma.sync.aligned.m16n8k16.row.col.f32.bf16.bf16.f32 "
                 "{%0,%1,%2,%3}, {%4,%5,%6,%7}, {%8,%9}, {%0,%1,%2,%3};"
                 : "+f"(d[0]), "+f"(d[1]), "+f"(d[2]), "+f"(d[3])
                 : "r"(a[0]), "r"(a[1]), "r"(a[2]), "r"(a[3]), "r"(b0), "r"(b1));
}

// store 4 fp32 values as split-bf16 triple at dst[0], dst[1024], dst[2048] (8B stores)
__device__ __forceinline__ void store_split4_A(__nv_bfloat16* dst, float4 v) {
    __nv_bfloat162 H0 = {__float2bfloat16(v.x), __float2bfloat16(v.y)};
    __nv_bfloat162 H1 = {__float2bfloat16(v.z), __float2bfloat16(v.w)};
    __nv_bfloat162 L0 = {__float2bfloat16(v.x - __bfloat162float(H0.x)),
                         __float2bfloat16(v.y - __bfloat162float(H0.y))};
    __nv_bfloat162 L1 = {__float2bfloat16(v.z - __bfloat162float(H1.x)),
                         __float2bfloat16(v.w - __bfloat162float(H1.y))};
    uint2 H = make_uint2(*(uint32_t*)&H0, *(uint32_t*)&H1);
    uint2 L = make_uint2(*(uint32_t*)&L0, *(uint32_t*)&L1);
    *(uint2*)&dst[0]    = H;
    *(uint2*)&dst[1024] = H;
    *(uint2*)&dst[2048] = L;
}

// ---------------- merged LN + weight conversion (one launch, 256 threads) ----------------
#define LN_BLKS (ROWS_X + ROWS_LAT)   /* 2624 */
__global__ void ln_convW(const float* __restrict__ x, const float* __restrict__ lat,
                         const float* __restrict__ g1, const float* __restrict__ b1,
                         const float* __restrict__ g2, const float* __restrict__ b2,
                         const float* __restrict__ Wq, const float* __restrict__ Wkv,
                         const float* __restrict__ Wout) {
    __shared__ float shmem[32 * 33];
    int tid = threadIdx.x;
    int blk = blockIdx.x;

    if (blk < LN_BLKS) {
        int row = blk;
        const float *src, *g, *b;
        __nv_bfloat16 *dst0, *dst1 = nullptr;
        if (row < ROWS_X) {
            int bb = row / N_KV, n = row % N_KV;
            src = x + (size_t)row * DD; g = g1; b = b1;
            dst0 = g_a3kv + (size_t)(bb * KV_PER_B + n) * K3;
        } else {
            int lr = row - ROWS_X;
            int bb = lr / N_Q, n = lr % N_Q;
            src = lat + (size_t)lr * DD; g = g2; b = b2;
            dst0 = g_a3small + (size_t)lr * K3;
            if (bb < B_X) dst1 = g_a3kv + (size_t)(bb * KV_PER_B + N_KV + n) * K3;
        }
        float4 v = ((const float4*)src)[tid];
        float s  = v.x + v.y + v.z + v.w;
        float ss = v.x*v.x + v.y*v.y + v.z*v.z + v.w*v.w;
        #pragma unroll
        for (int o = 16; o; o >>= 1) {
            s  += __shfl_xor_sync(0xFFFFFFFFu, s,  o);
            ss += __shfl_xor_sync(0xFFFFFFFFu, ss, o);
        }
        float* sb  = shmem;
        float* ssb = shmem + 8;
        int wid = tid >> 5, lane = tid & 31;
        if (lane == 0) { sb[wid] = s; ssb[wid] = ss; }
        __syncthreads();
        float ts = 0.f, tss = 0.f;
        #pragma unroll
        for (int i = 0; i < 8; i++) { ts += sb[i]; tss += ssb[i]; }
        float mean = ts * (1.0f / DD);
        float var  = tss * (1.0f / DD) - mean * mean;
        float inv  = rsqrtf(var + EPS);
        float4 gg = ((const float4*)g)[tid];
        float4 bb4 = ((const float4*)b)[tid];
        float4 o;
        o.x = (v.x - mean) * inv * gg.x + bb4.x;
        o.y = (v.y - mean) * inv * gg.y + bb4.y;
        o.z = (v.z - mean) * inv * gg.z + bb4.z;
        o.w = (v.w - mean) * inv * gg.w + bb4.w;
        store_split4_A(dst0 + tid * 4, o);
        if (dst1) store_split4_A(dst1 + tid * 4, o);
    } else {
        int t = blk - LN_BLKS;
        const float* W; __nv_bfloat16* dst; int N; int lt;
        if (t < 1024)      { W = Wq;   dst = g_w3q;   N = DD;     lt = t; }
        else if (t < 3072) { W = Wkv;  dst = g_w3kv;  N = 2 * DD; lt = t - 1024; }
        else               { W = Wout; dst = g_w3out; N = DD;     lt = t - 3072; }
        int ntiles_x = N / 32;
        int n0 = (lt % ntiles_x) * 32, k0 = (lt / ntiles_x) * 32;
        float (*tt)[33] = (float(*)[33])shmem;
        int tx = tid & 31, ty = tid >> 5;
        #pragma unroll
        for (int j = 0; j < 4; j++)
            tt[ty + j * 8][tx] = W[(size_t)(k0 + ty + j * 8) * N + n0 + tx];
        __syncthreads();
        #pragma unroll
        for (int j = 0; j < 4; j++) {
            int n = n0 + ty + j * 8, k = k0 + tx;
            float a = tt[tx][ty + j * 8];
            __nv_bfloat16 h = __float2bfloat16(a);
            __nv_bfloat16 l = __float2bfloat16(a - __bfloat162float(h));
            size_t o = (size_t)n * K3 + k;
            dst[o] = h; dst[o + 1024] = l; dst[o + 2048] = h;
        }
    }
}

// ---------------- redundancy-free split-bf16 GEMM core ----------------
// Per chunk c (32 K-elems of the base K=1024): load unique {Ah_c, Al_c, Wh_c, Wl_c}
// once, compute acc += Ah*Wh + Ah*Wl + Al*Wh. 4 chunk-loads per 3 mma passes
// (vs 6 in the duplicated-operand layout) -> 33% less smem/L2 traffic, same FLOPs.
#define GBK3 32
#define KST3 40                              /* padded row stride, bf16 elems (80 B) */
#define BUF3 (128 * KST3 * 2)                /* 10240 B per operand chunk */
#define STAGE3 (4 * BUF3)                    /* 40960 B */
#define GEMM3_SMEM (2 * STAGE3)              /* 81920 B */
#define NCH3 32                              /* 1024 / 32 chunks */

__device__ __forceinline__ void gemm_core3(const __nv_bfloat16* __restrict__ A3,
                                           const __nv_bfloat16* __restrict__ B3,
                                           float* __restrict__ C,
                                           int M, int N, int br, int bc,
                                           unsigned char* dynsm) {
    int tid = threadIdx.x, wid = tid >> 5, lane = tid & 31;
    int wm = (wid >> 2) * 64;
    int wn = (wid & 3) * 32;

    // chunk sources within the redundant layouts:
    //  Ah at col c*32          (A3 segment [0,1024))
    //  Al at col 2048 + c*32   (A3 segment [2048,3072))
    //  Wh at col c*32          (B3 segment [0,1024))
    //  Wl at col 1024 + c*32   (B3 segment [1024,2048))
    auto issue = [&](int c, int buf) {
        unsigned char* sb = dynsm + buf * STAGE3;
        #pragma unroll
        for (int j = 0; j < 8; j++) {
            int idx = tid + j * 256;           // 0..2047
            int op  = idx >> 9;                // 0:Ah 1:Al 2:Wh 3:Wl (uniform per j-pair)
            int rem = idx & 511;
            int r = rem >> 2, c4 = rem & 3;
            uint32_t dst = smem_u32(sb + op * BUF3 + (r * KST3 + c4 * 8) * 2);
            if (op < 2) {
                int gr = br + r; int sz = (gr < M) ? 16 : 0;
                if (gr >= M) gr = M - 1;
                int col = (op == 0 ? 0 : 2048) + c * GBK3 + c4 * 8;
                cp_async16(dst, A3 + (size_t)gr * K3 + col, sz);
            } else {
                int col = (op == 2 ? 0 : 1024) + c * GBK3 + c4 * 8;
                cp_async16(dst, B3 + (size_t)(bc + r) * K3 + col, 16);
            }
        }
        CP_COMMIT();
    };

    float acc[4][4][4] = {};

    issue(0, 0);
    CP_WAIT0();
    __syncthreads();

    for (int c = 0; c < NCH3; c++) {
        int cur = c & 1;
        if (c + 1 < NCH3) issue(c + 1, cur ^ 1);

        const unsigned char* sAh = dynsm + cur * STAGE3;
        const unsigned char* sAl = sAh + BUF3;
        const unsigned char* sWh = sAh + 2 * BUF3;
        const unsigned char* sWl = sAh + 3 * BUF3;

        #pragma unroll
        for (int ks = 0; ks < 2; ks++) {
            int k0 = ks * 16;
            int acol = k0 + (lane >> 4) * 8;
            int kcol = k0 + ((lane >> 3) & 1) * 8;

            uint32_t ah[4][4];
            #pragma unroll
            for (int mt = 0; mt < 4; mt++) {
                int arow = wm + mt * 16 + (lane & 15);
                ldm_x4(ah[mt], smem_u32(sAh + (arow * KST3 + acol) * 2));
            }
            uint32_t bh[2][4], bl[2][4];
            #pragma unroll
            for (int np = 0; np < 2; np++) {
                int nrow = wn + np * 16 + (lane & 7) + ((lane >> 4) << 3);
                ldm_x4(bh[np], smem_u32(sWh + (nrow * KST3 + kcol) * 2));
                ldm_x4(bl[np], smem_u32(sWl + (nrow * KST3 + kcol) * 2));
            }
            // Ah*Wh and Ah*Wl while ah is live
            #pragma unroll
            for (int mt = 0; mt < 4; mt++)
                #pragma unroll
                for (int nt = 0; nt < 4; nt++) {
                    mma_bf16(acc[mt][nt], ah[mt], bh[nt >> 1][(nt & 1) * 2],
                             bh[nt >> 1][(nt & 1) * 2 + 1]);
                    mma_bf16(acc[mt][nt], ah[mt], bl[nt >> 1][(nt & 1) * 2],
                             bl[nt >> 1][(nt & 1) * 2 + 1]);
                }
            // Al*Wh (ah dead, reuse pressure)
            uint32_t al[4][4];
            #pragma unroll
            for (int mt = 0; mt < 4; mt++) {
                int arow = wm + mt * 16 + (lane & 15);
                ldm_x4(al[mt], smem_u32(sAl + (arow * KST3 + acol) * 2));
            }
            #pragma unroll
            for (int mt = 0; mt < 4; mt++)
                #pragma unroll
                for (int nt = 0; nt < 4; nt++)
                    mma_bf16(acc[mt][nt], al[mt], bh[nt >> 1][(nt & 1) * 2],
                             bh[nt >> 1][(nt & 1) * 2 + 1]);
        }
        if (c + 1 < NCH3) CP_WAIT0();
        __syncthreads();
    }

    #pragma unroll
    for (int mt = 0; mt < 4; mt++) {
        int r0 = br + wm + mt * 16 + (lane >> 2);
        #pragma unroll
        for (int nt = 0; nt < 4; nt++) {
            int c2 = bc + wn + nt * 8 + (lane & 3) * 2;
            if (r0 < M)
                *(float2*)&C[(size_t)r0 * N + c2] = make_float2(acc[mt][nt][0], acc[mt][nt][1]);
            if (r0 + 8 < M)
                *(float2*)&C[(size_t)(r0 + 8) * N + c2] = make_float2(acc[mt][nt][2], acc[mt][nt][3]);
        }
    }
}

// ---------------- 64-row-tile GEMM core (output projection; R12-proven) ----------------
#define GBK 64
#define KST 72
#define ABUF (128 * KST * 2)
#define ABUF64 (64 * KST * 2)
#define STAGE64 (ABUF64 + ABUF)
#define GEMM64_SMEM (2 * STAGE64)            /* 55296 B */
#define NCH (K3 / GBK)                       /* 48 */

__device__ __forceinline__ void gemm_core64(const __nv_bfloat16* __restrict__ A3,
                                            const __nv_bfloat16* __restrict__ B3,
                                            float* __restrict__ C,
                                            int M, int N, int br, int bc,
                                            unsigned char* dynsm) {
    int tid = threadIdx.x, wid = tid >> 5, lane = tid & 31;
    int wm = (wid >> 2) * 32;
    int wn = (wid & 3) * 32;

    auto issue = [&](int kb, int buf) {
        unsigned char* sb = dynsm + buf * STAGE64;
        const __nv_bfloat16* Ab = A3 + kb * GBK;
        const __nv_bfloat16* Bb = B3 + (size_t)bc * K3 + kb * GBK;
        #pragma unroll
        for (int j = 0; j < 2; j++) {
            int idx = tid + j * 256;
            int r = idx >> 3, c8 = idx & 7;
            int gr = br + r; int sz = (gr < M) ? 16 : 0;
            if (gr >= M) gr = M - 1;
            cp_async16(smem_u32(sb + (r * KST + c8 * 8) * 2),
                       Ab + (size_t)gr * K3 + c8 * 8, sz);
        }
        #pragma unroll
        for (int j = 0; j < 4; j++) {
            int idx = tid + j * 256;
            int r = idx >> 3, c8 = idx & 7;
            cp_async16(smem_u32(sb + ABUF64 + (r * KST + c8 * 8) * 2),
                       Bb + (size_t)r * K3 + c8 * 8, 16);
        }
        CP_COMMIT();
    };

    float acc[2][4][4] = {};

    issue(0, 0);
    CP_WAIT0();
    __syncthreads();

    for (int kb = 0; kb < NCH; kb++) {
        int cur = kb & 1;
        if (kb + 1 < NCH) issue(kb + 1, cur ^ 1);

        const unsigned char* sA = dynsm + cur * STAGE64;
        const unsigned char* sB = sA + ABUF64;
        #pragma unroll
        for (int ks = 0; ks < 4; ks++) {
            int k0 = ks * 16;
            uint32_t a[2][4];
            #pragma unroll
            for (int mt = 0; mt < 2; mt++) {
                int arow = wm + mt * 16 + (lane & 15);
                int acol = k0 + (lane >> 4) * 8;
                ldm_x4(a[mt], smem_u32(sA + (arow * KST + acol) * 2));
            }
            uint32_t b[2][4];
            #pragma unroll
            for (int np = 0; np < 2; np++) {
                int nrow = wn + np * 16 + (lane & 7) + ((lane >> 4) << 3);
                int kcol = k0 + ((lane >> 3) & 1) * 8;
                ldm_x4(b[np], smem_u32(sB + (nrow * KST + kcol) * 2));
            }
            #pragma unroll
            for (int mt = 0; mt < 2; mt++)
                #pragma unroll
                for (int nt = 0; nt < 4; nt++)
                    mma_bf16(acc[mt][nt], a[mt], b[nt >> 1][(nt & 1) * 2],
                             b[nt >> 1][(nt & 1) * 2 + 1]);
        }
        if (kb + 1 < NCH) CP_WAIT0();
        __syncthreads();
    }

    #pragma unroll
    for (int mt = 0; mt < 2; mt++) {
        int r0 = br + wm + mt * 16 + (lane >> 2);
        #pragma unroll
        for (int nt = 0; nt < 4; nt++) {
            int c = bc + wn + nt * 8 + (lane & 3) * 2;
            if (r0 < M)
                *(float2*)&C[(size_t)r0 * N + c] = make_float2(acc[mt][nt][0], acc[mt][nt][1]);
            if (r0 + 8 < M)
                *(float2*)&C[(size_t)(r0 + 8) * N + c] = make_float2(acc[mt][nt][2], acc[mt][nt][3]);
        }
    }
}

// merged Q + KV projection: KV tiles (320) first, then Q tiles (40); full K per CTA
#define KV_TILES 320
#define Q_TILES  40

__global__ __launch_bounds__(256, 2)
void gemm_qkv() {
    extern __shared__ __align__(16) unsigned char dynsm[];
    int bid = blockIdx.x;
    if (bid < KV_TILES) {
        int bx = bid & 15, by = bid >> 4;
        gemm_core3(g_a3kv, g_w3kv, g_kv, ROWS_KV, 2 * DD, by * 128, bx * 128, dynsm);
    } else {
        int t = bid - KV_TILES;
        int bx = t & 7, by = t >> 3;
        gemm_core3(g_a3small, g_w3q, g_q, ROWS_LAT, DD, by * 128, bx * 128, dynsm);
    }
}

__global__ __launch_bounds__(256)
void gemm_out(float* __restrict__ C) {
    extern __shared__ __align__(16) unsigned char dynsm[];
    gemm_core64(g_a3small, g_w3out, C, ROWS_LAT, DD, blockIdx.y * 64, blockIdx.x * 128, dynsm);
}

// ---------------- attention: one block per 64-key subtile, single-pass softmax ----------------
// (verbatim R12 version)
#define ASTR 68

__global__ __launch_bounds__(256)
void attn_part(const int* __restrict__ um_p) {
    int s  = blockIdx.x;
    int h  = blockIdx.y;
    int qb = blockIdx.z;
    int um = *um_p;
    bool masked = (um != 0) && (qb < B_X);
    if (masked && s >= 5) return;   // whole block exits before any barrier
    int kbase = masked ? (qb * KV_PER_B + s * 64) : (s * 64);

    extern __shared__ float smf[];
    float* Qs = smf;                    // [d][q] pre-scaled
    float* Ks = smf + 64 * ASTR;        // [d][k]
    float* Vs = smf + 2 * 64 * ASTR;    // [k][d]
    float* Ps = smf + 3 * 64 * ASTR;    // [q][k]
    float* mrow = smf + 4 * 64 * ASTR;  // [64]
    float* lrow = mrow + 64;

    int tid = threadIdx.x;
    int ty = tid >> 4, tx = tid & 15;

    #pragma unroll
    for (int it = 0; it < 4; it++) {
        int row = ty + it * 16;
        int col = tx * 4;
        float4 v = *(const float4*)&g_q[(size_t)(qb * 64 + row) * DD + h * DH + col];
        Qs[(col + 0) * ASTR + row] = v.x * 0.125f;
        Qs[(col + 1) * ASTR + row] = v.y * 0.125f;
        Qs[(col + 2) * ASTR + row] = v.z * 0.125f;
        Qs[(col + 3) * ASTR + row] = v.w * 0.125f;
        const float* base = g_kv + (size_t)(kbase + row) * (2 * DD) + h * DH + col;
        float4 kk = *(const float4*)base;
        Ks[(col + 0) * ASTR + row] = kk.x;
        Ks[(col + 1) * ASTR + row] = kk.y;
        Ks[(col + 2) * ASTR + row] = kk.z;
        Ks[(col + 3) * ASTR + row] = kk.w;
        *(float4*)&Vs[row * ASTR + col] = *(const float4*)(base + DD);
    }
    __syncthreads();

    float sacc[4][4] = {};
    #pragma unroll
    for (int d = 0; d < 64; d++) {
        float4 aq = *(const float4*)&Qs[d * ASTR + ty * 4];
        float4 bk = *(const float4*)&Ks[d * ASTR + tx * 4];
        sacc[0][0] += aq.x * bk.x; sacc[0][1] += aq.x * bk.y;
        sacc[0][2] += aq.x * bk.z; sacc[0][3] += aq.x * bk.w;
        sacc[1][0] += aq.y * bk.x; sacc[1][1] += aq.y * bk.y;
        sacc[1][2] += aq.y * bk.z; sacc[1][3] += aq.y * bk.w;
        sacc[2][0] += aq.z * bk.x; sacc[2][1] += aq.z * bk.y;
        sacc[2][2] += aq.z * bk.z; sacc[2][3] += aq.z * bk.w;
        sacc[3][0] += aq.w * bk.x; sacc[3][1] += aq.w * bk.y;
        sacc[3][2] += aq.w * bk.z; sacc[3][3] += aq.w * bk.w;
    }
    #pragma unroll
    for (int i = 0; i < 4; i++)
        #pragma unroll
        for (int j = 0; j < 4; j++)
            Ps[(ty * 4 + i) * ASTR + tx * 4 + j] = sacc[i][j];
    __syncthreads();

    {
        int r = tid >> 2, part = tid & 3;
        float rm = -INFINITY;
        #pragma unroll
        for (int i = 0; i < 16; i++)
            rm = fmaxf(rm, Ps[r * ASTR + part * 16 + i]);
        rm = fmaxf(rm, __shfl_xor_sync(0xFFFFFFFFu, rm, 1));
        rm = fmaxf(rm, __shfl_xor_sync(0xFFFFFFFFu, rm, 2));
        float psum = 0.f;
        #pragma unroll
        for (int i = 0; i < 16; i++) {
            float p = __expf(Ps[r * ASTR + part * 16 + i] - rm);
            Ps[r * ASTR + part * 16 + i] = p;
            psum += p;
        }
        psum += __shfl_xor_sync(0xFFFFFFFFu, psum, 1);
        psum += __shfl_xor_sync(0xFFFFFFFFu, psum, 2);
        if (part == 0) { mrow[r] = rm; lrow[r] = psum; }
    }
    __syncthreads();

    float oacc[4][4] = {};
    #pragma unroll
    for (int k = 0; k < 64; k++) {
        float4 v4 = *(const float4*)&Vs[k * ASTR + tx * 4];
        float p0 = Ps[(ty * 4 + 0) * ASTR + k];
        float p1 = Ps[(ty * 4 + 1) * ASTR + k];
        float p2 = Ps[(ty * 4 + 2) * ASTR + k];
        float p3 = Ps[(ty * 4 + 3) * ASTR + k];
        oacc[0][0] += p0 * v4.x; oacc[0][1] += p0 * v4.y;
        oacc[0][2] += p0 * v4.z; oacc[0][3] += p0 * v4.w;
        oacc[1][0] += p1 * v4.x; oacc[1][1] += p1 * v4.y;
        oacc[1][2] += p1 * v4.z; oacc[1][3] += p1 * v4.w;
        oacc[2][0] += p2 * v4.x; oacc[2][1] += p2 * v4.y;
        oacc[2][2] += p2 * v4.z; oacc[2][3] += p2 * v4.w;
        oacc[3][0] += p3 * v4.x; oacc[3][1] += p3 * v4.y;
        oacc[3][2] += p3 * v4.z; oacc[3][3] += p3 * v4.w;
    }

    int pidx = (qb * HEADS + h) * NSUB + s;
    #pragma unroll
    for (int i = 0; i < 4; i++) {
        float4 o = make_float4(oacc[i][0], oacc[i][1], oacc[i][2], oacc[i][3]);
        *(float4*)&g_pO[((size_t)pidx * 64 + ty * 4 + i) * 64 + tx * 4] = o;
    }
    if (tid < 64) {
        g_pm[pidx * 64 + tid] = mrow[tid];
        g_pl[pidx * 64 + tid] = lrow[tid];
    }
}

// merge partials per (q,h) row: 5 (masked, qb<8) or 40 (dense); streaming
__global__ __launch_bounds__(256)
void attn_combine(const int* __restrict__ um_p) {
    int q = blockIdx.x * 4 + (threadIdx.x >> 6);
    int h = blockIdx.y;
    int qb = q >> 6, qq = q & 63;
    int um = *um_p;
    bool masked = (um != 0) && (qb < B_X);
    int ns = masked ? 5 : NSUB;
    int d = threadIdx.x & 63;
    int pbase = (qb * HEADS + h) * NSUB;

    float M = -INFINITY;
    for (int c = 0; c < ns; c++)
        M = fmaxf(M, g_pm[(pbase + c) * 64 + qq]);
    float L = 0.f, o = 0.f;
    for (int c = 0; c < ns; c++) {
        float e = __expf(g_pm[(pbase + c) * 64 + qq] - M);
        L += g_pl[(pbase + c) * 64 + qq] * e;
        o += g_pO[((size_t)(pbase + c) * 64 + qq) * 64 + d] * e;
    }
    float r = o / L;
    __nv_bfloat16 hh = __float2bfloat16(r);
    __nv_bfloat16 ll = __float2bfloat16(r - __bfloat162float(hh));
    __nv_bfloat16* dst = g_a3small + (size_t)q * K3 + h * DH + d;
    dst[0] = hh; dst[1024] = hh; dst[2048] = ll;
}

// ---------------- launch ----------------
#define ATTN_SMEM ((4 * 64 * ASTR + 192) * (int)sizeof(float))   /* 70400 B */

extern "C" void kernel_launch(void* const* d_in, const int* in_sizes, int n_in,
                              void* d_out, int out_size) {
    const float* x    = (const float*)d_in[0];
    const float* lat  = (const float*)d_in[1];
    const float* g1   = (const float*)d_in[2];
    const float* b1   = (const float*)d_in[3];
    const float* g2   = (const float*)d_in[4];
    const float* b2   = (const float*)d_in[5];
    const float* Wq   = (const float*)d_in[6];
    const float* Wkv  = (const float*)d_in[7];
    const float* Wout = (const float*)d_in[8];
    const int*   um   = (const int*)d_in[9];
    float* out = (float*)d_out;

    cudaFuncSetAttribute(gemm_qkv,  cudaFuncAttributeMaxDynamicSharedMemorySize, GEMM3_SMEM);
    cudaFuncSetAttribute(gemm_out,  cudaFuncAttributeMaxDynamicSharedMemorySize, GEMM64_SMEM);
    cudaFuncSetAttribute(attn_part, cudaFuncAttributeMaxDynamicSharedMemorySize, ATTN_SMEM);

    // 1. LayerNorm + all weight conversions in ONE launch
    ln_convW<<<LN_BLKS + 4096, 256>>>(x, lat, g1, b1, g2, b2, Wq, Wkv, Wout);

    // 2. Q + KV projections (redundancy-free chunk loads, 360 CTAs, full K)
    gemm_qkv<<<KV_TILES + Q_TILES, 256, GEMM3_SMEM>>>();

    // 3. attention partials (R12-proven kernel) + streaming combine
    attn_part<<<dim3(NSUB, HEADS, B_LAT), 256, ATTN_SMEM>>>(um);
    attn_combine<<<dim3(ROWS_LAT / 4, HEADS), 256>>>(um);

    // 4. output projection (64-row tiles, 72 CTAs)
    gemm_out<<<dim3(DD / 128, ROWS_LAT / 64), 256, GEMM64_SMEM>>>(out);
}

// round 17
// speedup vs baseline: 1.0816x; 1.0073x over previous
#include <cuda_runtime.h>
#include <cuda_bf16.h>
#include <math.h>
#include <stdint.h>

#define DD 1024
#define HEADS 16
#define DH 64
#define B_LAT 9
#define B_X 8
#define N_KV 256
#define N_Q 64
#define KV_PER_B (N_KV + N_Q)       /* 320  */
#define ROWS_X (B_X * N_KV)         /* 2048 */
#define ROWS_LAT (B_LAT * N_Q)      /* 576  */
#define ROWS_KV (B_X * KV_PER_B)    /* 2560 */
#define EPS 1e-5f
#define NSUB 40                     /* 2560/64 key subtiles */
#define NPART40 (B_LAT * HEADS * NSUB)   /* 5760 */
#define K3 3072                     /* split-bf16 extended K = 3*1024 */

// ---------------- scratch (static device globals; no allocation) ----------------
__device__ float g_q[ROWS_LAT * DD];
__device__ float g_kv[ROWS_KV * 2 * DD];
__device__ float g_pO[(size_t)NPART40 * 64 * 64];   /* 94.4 MB */
__device__ float g_pm[NPART40 * 64];
__device__ float g_pl[NPART40 * 64];
// split-bf16 operands (sparse layout): A: h at col [0,1024), l at [2048,3072);
// W: h at [0,1024), l at [1024,2048). Middle/tail duplicates no longer written.
__device__ __nv_bfloat16 g_a3kv[(size_t)ROWS_KV * K3];
__device__ __nv_bfloat16 g_a3small[(size_t)ROWS_LAT * K3];   // lnlat splits, later ao splits
__device__ __nv_bfloat16 g_w3q[(size_t)DD * K3];
__device__ __nv_bfloat16 g_w3kv[(size_t)(2 * DD) * K3];
__device__ __nv_bfloat16 g_w3out[(size_t)DD * K3];

// ---------------- PTX helpers (base ISA only: sm_80-compatible) ----------------
__device__ __forceinline__ uint32_t smem_u32(const void* p) {
    uint32_t a;
    asm("{ .reg .u64 t; cvta.to.shared.u64 t, %1; cvt.u32.u64 %0, t; }" : "=r"(a) : "l"(p));
    return a;
}
__device__ __forceinline__ void cp_async16(uint32_t s, const void* g, int sz) {
    asm volatile("cp.async.cg.shared.global [%0], [%1], 16, %2;"
                 :: "r"(s), "l"(g), "r"(sz) : "memory");
}
#define CP_COMMIT()  asm volatile("cp.async.commit_group;" ::: "memory")
#define CP_WAIT0()   asm volatile("cp.async.wait_group 0;" ::: "memory")

__device__ __forceinline__ void ldm_x4(uint32_t* r, uint32_t a) {
    asm volatile("ldmatrix.sync.aligned.m8n8.x4.shared.b16 {%0,%1,%2,%3}, [%4];"
                 : "=r"(r[0]), "=r"(r[1]), "=r"(r[2]), "=r"(r[3]) : "r"(a));
}
__device__ __forceinline__ void mma_bf16(float* d, const uint32_t* a, uint32_t b0, uint32_t b1) {
    asm volatile("mma.sync.aligned.m16n8k16.row.col.f32.bf16.bf16.f32 "
                 "{%0,%1,%2,%3}, {%4,%5,%6,%7}, {%8,%9}, {%0,%1,%2,%3};"
                 : "+f"(d[0]), "+f"(d[1]), "+f"(d[2]), "+f"(d[3])
                 : "r"(a[0]), "r"(a[1]), "r"(a[2]), "r"(a[3]), "r"(b0), "r"(b1));
}

// store 4 fp32 values as split-bf16 pair at dst[0] (high) and dst[2048] (low)
__device__ __forceinline__ void store_split4_A(__nv_bfloat16* dst, float4 v) {
    __nv_bfloat162 H0 = {__float2bfloat16(v.x), __float2bfloat16(v.y)};
    __nv_bfloat162 H1 = {__float2bfloat16(v.z), __float2bfloat16(v.w)};
    __nv_bfloat162 L0 = {__float2bfloat16(v.x - __bfloat162float(H0.x)),
                         __float2bfloat16(v.y - __bfloat162float(H0.y))};
    __nv_bfloat162 L1 = {__float2bfloat16(v.z - __bfloat162float(H1.x)),
                         __float2bfloat16(v.w - __bfloat162float(H1.y))};
    uint2 H = make_uint2(*(uint32_t*)&H0, *(uint32_t*)&H1);
    uint2 L = make_uint2(*(uint32_t*)&L0, *(uint32_t*)&L1);
    *(uint2*)&dst[0]    = H;
    *(uint2*)&dst[2048] = L;
}

// ---------------- merged LN + weight conversion (one launch, 256 threads) ----------------
#define LN_BLKS (ROWS_X + ROWS_LAT)   /* 2624 */
__global__ void ln_convW(const float* __restrict__ x, const float* __restrict__ lat,
                         const float* __restrict__ g1, const float* __restrict__ b1,
                         const float* __restrict__ g2, const float* __restrict__ b2,
                         const float* __restrict__ Wq, const float* __restrict__ Wkv,
                         const float* __restrict__ Wout) {
    __shared__ float shmem[32 * 33];
    int tid = threadIdx.x;
    int blk = blockIdx.x;

    if (blk < LN_BLKS) {
        int row = blk;
        const float *src, *g, *b;
        __nv_bfloat16 *dst0, *dst1 = nullptr;
        if (row < ROWS_X) {
            int bb = row / N_KV, n = row % N_KV;
            src = x + (size_t)row * DD; g = g1; b = b1;
            dst0 = g_a3kv + (size_t)(bb * KV_PER_B + n) * K3;
        } else {
            int lr = row - ROWS_X;
            int bb = lr / N_Q, n = lr % N_Q;
            src = lat + (size_t)lr * DD; g = g2; b = b2;
            dst0 = g_a3small + (size_t)lr * K3;
            if (bb < B_X) dst1 = g_a3kv + (size_t)(bb * KV_PER_B + N_KV + n) * K3;
        }
        float4 v = ((const float4*)src)[tid];
        float s  = v.x + v.y + v.z + v.w;
        float ss = v.x*v.x + v.y*v.y + v.z*v.z + v.w*v.w;
        #pragma unroll
        for (int o = 16; o; o >>= 1) {
            s  += __shfl_xor_sync(0xFFFFFFFFu, s,  o);
            ss += __shfl_xor_sync(0xFFFFFFFFu, ss, o);
        }
        float* sb  = shmem;
        float* ssb = shmem + 8;
        int wid = tid >> 5, lane = tid & 31;
        if (lane == 0) { sb[wid] = s; ssb[wid] = ss; }
        __syncthreads();
        float ts = 0.f, tss = 0.f;
        #pragma unroll
        for (int i = 0; i < 8; i++) { ts += sb[i]; tss += ssb[i]; }
        float mean = ts * (1.0f / DD);
        float var  = tss * (1.0f / DD) - mean * mean;
        float inv  = rsqrtf(var + EPS);
        float4 gg = ((const float4*)g)[tid];
        float4 bb4 = ((const float4*)b)[tid];
        float4 o;
        o.x = (v.x - mean) * inv * gg.x + bb4.x;
        o.y = (v.y - mean) * inv * gg.y + bb4.y;
        o.z = (v.z - mean) * inv * gg.z + bb4.z;
        o.w = (v.w - mean) * inv * gg.w + bb4.w;
        store_split4_A(dst0 + tid * 4, o);
        if (dst1) store_split4_A(dst1 + tid * 4, o);
    } else {
        int t = blk - LN_BLKS;
        const float* W; __nv_bfloat16* dst; int N; int lt;
        if (t < 1024)      { W = Wq;   dst = g_w3q;   N = DD;     lt = t; }
        else if (t < 3072) { W = Wkv;  dst = g_w3kv;  N = 2 * DD; lt = t - 1024; }
        else               { W = Wout; dst = g_w3out; N = DD;     lt = t - 3072; }
        int ntiles_x = N / 32;
        int n0 = (lt % ntiles_x) * 32, k0 = (lt / ntiles_x) * 32;
        float (*tt)[33] = (float(*)[33])shmem;
        int tx = tid & 31, ty = tid >> 5;
        #pragma unroll
        for (int j = 0; j < 4; j++)
            tt[ty + j * 8][tx] = W[(size_t)(k0 + ty + j * 8) * N + n0 + tx];
        __syncthreads();
        #pragma unroll
        for (int j = 0; j < 4; j++) {
            int n = n0 + ty + j * 8, k = k0 + tx;
            float a = tt[tx][ty + j * 8];
            __nv_bfloat16 h = __float2bfloat16(a);
            __nv_bfloat16 l = __float2bfloat16(a - __bfloat162float(h));
            size_t o = (size_t)n * K3 + k;
            dst[o] = h; dst[o + 1024] = l;
        }
    }
}

// ---------------- redundancy-free split-bf16 GEMM core (128-row tiles; R16-proven) ----------------
#define GBK3 32
#define KST3 40                              /* padded row stride, bf16 elems (80 B) */
#define BUF3 (128 * KST3 * 2)                /* 10240 B per operand chunk */
#define STAGE3 (4 * BUF3)                    /* 40960 B */
#define GEMM3_SMEM (2 * STAGE3)              /* 81920 B */
#define NCH3 32                              /* 1024 / 32 chunks */

__device__ __forceinline__ void gemm_core3(const __nv_bfloat16* __restrict__ A3,
                                           const __nv_bfloat16* __restrict__ B3,
                                           float* __restrict__ C,
                                           int M, int N, int br, int bc,
                                           unsigned char* dynsm) {
    int tid = threadIdx.x, wid = tid >> 5, lane = tid & 31;
    int wm = (wid >> 2) * 64;
    int wn = (wid & 3) * 32;

    auto issue = [&](int c, int buf) {
        unsigned char* sb = dynsm + buf * STAGE3;
        #pragma unroll
        for (int j = 0; j < 8; j++) {
            int idx = tid + j * 256;           // 0..2047
            int op  = idx >> 9;                // 0:Ah 1:Al 2:Wh 3:Wl
            int rem = idx & 511;
            int r = rem >> 2, c4 = rem & 3;
            uint32_t dst = smem_u32(sb + op * BUF3 + (r * KST3 + c4 * 8) * 2);
            if (op < 2) {
                int gr = br + r; int sz = (gr < M) ? 16 : 0;
                if (gr >= M) gr = M - 1;
                int col = (op == 0 ? 0 : 2048) + c * GBK3 + c4 * 8;
                cp_async16(dst, A3 + (size_t)gr * K3 + col, sz);
            } else {
                int col = (op == 2 ? 0 : 1024) + c * GBK3 + c4 * 8;
                cp_async16(dst, B3 + (size_t)(bc + r) * K3 + col, 16);
            }
        }
        CP_COMMIT();
    };

    float acc[4][4][4] = {};

    issue(0, 0);
    CP_WAIT0();
    __syncthreads();

    for (int c = 0; c < NCH3; c++) {
        int cur = c & 1;
        if (c + 1 < NCH3) issue(c + 1, cur ^ 1);

        const unsigned char* sAh = dynsm + cur * STAGE3;
        const unsigned char* sAl = sAh + BUF3;
        const unsigned char* sWh = sAh + 2 * BUF3;
        const unsigned char* sWl = sAh + 3 * BUF3;

        #pragma unroll
        for (int ks = 0; ks < 2; ks++) {
            int k0 = ks * 16;
            int acol = k0 + (lane >> 4) * 8;
            int kcol = k0 + ((lane >> 3) & 1) * 8;

            uint32_t ah[4][4];
            #pragma unroll
            for (int mt = 0; mt < 4; mt++) {
                int arow = wm + mt * 16 + (lane & 15);
                ldm_x4(ah[mt], smem_u32(sAh + (arow * KST3 + acol) * 2));
            }
            uint32_t bh[2][4], bl[2][4];
            #pragma unroll
            for (int np = 0; np < 2; np++) {
                int nrow = wn + np * 16 + (lane & 7) + ((lane >> 4) << 3);
                ldm_x4(bh[np], smem_u32(sWh + (nrow * KST3 + kcol) * 2));
                ldm_x4(bl[np], smem_u32(sWl + (nrow * KST3 + kcol) * 2));
            }
            #pragma unroll
            for (int mt = 0; mt < 4; mt++)
                #pragma unroll
                for (int nt = 0; nt < 4; nt++) {
                    mma_bf16(acc[mt][nt], ah[mt], bh[nt >> 1][(nt & 1) * 2],
                             bh[nt >> 1][(nt & 1) * 2 + 1]);
                    mma_bf16(acc[mt][nt], ah[mt], bl[nt >> 1][(nt & 1) * 2],
                             bl[nt >> 1][(nt & 1) * 2 + 1]);
                }
            uint32_t al[4][4];
            #pragma unroll
            for (int mt = 0; mt < 4; mt++) {
                int arow = wm + mt * 16 + (lane & 15);
                ldm_x4(al[mt], smem_u32(sAl + (arow * KST3 + acol) * 2));
            }
            #pragma unroll
            for (int mt = 0; mt < 4; mt++)
                #pragma unroll
                for (int nt = 0; nt < 4; nt++)
                    mma_bf16(acc[mt][nt], al[mt], bh[nt >> 1][(nt & 1) * 2],
                             bh[nt >> 1][(nt & 1) * 2 + 1]);
        }
        if (c + 1 < NCH3) CP_WAIT0();
        __syncthreads();
    }

    #pragma unroll
    for (int mt = 0; mt < 4; mt++) {
        int r0 = br + wm + mt * 16 + (lane >> 2);
        #pragma unroll
        for (int nt = 0; nt < 4; nt++) {
            int c2 = bc + wn + nt * 8 + (lane & 3) * 2;
            if (r0 < M)
                *(float2*)&C[(size_t)r0 * N + c2] = make_float2(acc[mt][nt][0], acc[mt][nt][1]);
            if (r0 + 8 < M)
                *(float2*)&C[(size_t)(r0 + 8) * N + c2] = make_float2(acc[mt][nt][2], acc[mt][nt][3]);
        }
    }
}

// ---------------- redundancy-free 64-row-tile core (output projection) ----------------
#define BUF3A64 (64 * KST3 * 2)              /* 5120 B */
#define STAGE3_64 (2 * BUF3A64 + 2 * BUF3)   /* 30720 B */
#define GEMM3_64_SMEM (2 * STAGE3_64)        /* 61440 B */

__device__ __forceinline__ void gemm_core3_64(const __nv_bfloat16* __restrict__ A3,
                                              const __nv_bfloat16* __restrict__ B3,
                                              float* __restrict__ C,
                                              int M, int N, int br, int bc,
                                              unsigned char* dynsm) {
    int tid = threadIdx.x, wid = tid >> 5, lane = tid & 31;
    int wm = (wid >> 2) * 32;
    int wn = (wid & 3) * 32;

    auto issue = [&](int c, int buf) {
        unsigned char* sb = dynsm + buf * STAGE3_64;
        #pragma unroll
        for (int j = 0; j < 6; j++) {
            int idx = tid + j * 256;           // 0..1535
            if (idx < 512) {
                int op = idx >> 8;             // 0:Ah 1:Al
                int rem = idx & 255;
                int r = rem >> 2, c4 = rem & 3;
                int gr = br + r; int sz = (gr < M) ? 16 : 0;
                if (gr >= M) gr = M - 1;
                int col = (op == 0 ? 0 : 2048) + c * GBK3 + c4 * 8;
                cp_async16(smem_u32(sb + op * BUF3A64 + (r * KST3 + c4 * 8) * 2),
                           A3 + (size_t)gr * K3 + col, sz);
            } else {
                int rem = idx - 512;           // 0..1023
                int op = rem >> 9;             // 0:Wh 1:Wl
                int rem2 = rem & 511;
                int r = rem2 >> 2, c4 = rem2 & 3;
                int col = (op == 0 ? 0 : 1024) + c * GBK3 + c4 * 8;
                cp_async16(smem_u32(sb + 2 * BUF3A64 + op * BUF3 + (r * KST3 + c4 * 8) * 2),
                           B3 + (size_t)(bc + r) * K3 + col, 16);
            }
        }
        CP_COMMIT();
    };

    float acc[2][4][4] = {};

    issue(0, 0);
    CP_WAIT0();
    __syncthreads();

    for (int c = 0; c < NCH3; c++) {
        int cur = c & 1;
        if (c + 1 < NCH3) issue(c + 1, cur ^ 1);

        const unsigned char* sAh = dynsm + cur * STAGE3_64;
        const unsigned char* sAl = sAh + BUF3A64;
        const unsigned char* sWh = sAh + 2 * BUF3A64;
        const unsigned char* sWl = sWh + BUF3;

        #pragma unroll
        for (int ks = 0; ks < 2; ks++) {
            int k0 = ks * 16;
            int acol = k0 + (lane >> 4) * 8;
            int kcol = k0 + ((lane >> 3) & 1) * 8;

            uint32_t ah[2][4];
            #pragma unroll
            for (int mt = 0; mt < 2; mt++) {
                int arow = wm + mt * 16 + (lane & 15);
                ldm_x4(ah[mt], smem_u32(sAh + (arow * KST3 + acol) * 2));
            }
            uint32_t bh[2][4], bl[2][4];
            #pragma unroll
            for (int np = 0; np < 2; np++) {
                int nrow = wn + np * 16 + (lane & 7) + ((lane >> 4) << 3);
                ldm_x4(bh[np], smem_u32(sWh + (nrow * KST3 + kcol) * 2));
                ldm_x4(bl[np], smem_u32(sWl + (nrow * KST3 + kcol) * 2));
            }
            #pragma unroll
            for (int mt = 0; mt < 2; mt++)
                #pragma unroll
                for (int nt = 0; nt < 4; nt++) {
                    mma_bf16(acc[mt][nt], ah[mt], bh[nt >> 1][(nt & 1) * 2],
                             bh[nt >> 1][(nt & 1) * 2 + 1]);
                    mma_bf16(acc[mt][nt], ah[mt], bl[nt >> 1][(nt & 1) * 2],
                             bl[nt >> 1][(nt & 1) * 2 + 1]);
                }
            uint32_t al[2][4];
            #pragma unroll
            for (int mt = 0; mt < 2; mt++) {
                int arow = wm + mt * 16 + (lane & 15);
                ldm_x4(al[mt], smem_u32(sAl + (arow * KST3 + acol) * 2));
            }
            #pragma unroll
            for (int mt = 0; mt < 2; mt++)
                #pragma unroll
                for (int nt = 0; nt < 4; nt++)
                    mma_bf16(acc[mt][nt], al[mt], bh[nt >> 1][(nt & 1) * 2],
                             bh[nt >> 1][(nt & 1) * 2 + 1]);
        }
        if (c + 1 < NCH3) CP_WAIT0();
        __syncthreads();
    }

    #pragma unroll
    for (int mt = 0; mt < 2; mt++) {
        int r0 = br + wm + mt * 16 + (lane >> 2);
        #pragma unroll
        for (int nt = 0; nt < 4; nt++) {
            int c2 = bc + wn + nt * 8 + (lane & 3) * 2;
            if (r0 < M)
                *(float2*)&C[(size_t)r0 * N + c2] = make_float2(acc[mt][nt][0], acc[mt][nt][1]);
            if (r0 + 8 < M)
                *(float2*)&C[(size_t)(r0 + 8) * N + c2] = make_float2(acc[mt][nt][2], acc[mt][nt][3]);
        }
    }
}

// merged Q + KV projection: KV tiles (320) first, then Q tiles (40); full K per CTA
#define KV_TILES 320
#define Q_TILES  40

__global__ __launch_bounds__(256, 2)
void gemm_qkv() {
    extern __shared__ __align__(16) unsigned char dynsm[];
    int bid = blockIdx.x;
    if (bid < KV_TILES) {
        int bx = bid & 15, by = bid >> 4;
        gemm_core3(g_a3kv, g_w3kv, g_kv, ROWS_KV, 2 * DD, by * 128, bx * 128, dynsm);
    } else {
        int t = bid - KV_TILES;
        int bx = t & 7, by = t >> 3;
        gemm_core3(g_a3small, g_w3q, g_q, ROWS_LAT, DD, by * 128, bx * 128, dynsm);
    }
}

__global__ __launch_bounds__(256)
void gemm_out(float* __restrict__ C) {
    extern __shared__ __align__(16) unsigned char dynsm[];
    gemm_core3_64(g_a3small, g_w3out, C, ROWS_LAT, DD, blockIdx.y * 64, blockIdx.x * 128, dynsm);
}

// ---------------- attention: one block per 64-key subtile, single-pass softmax ----------------
// (verbatim R12/R16 version)
#define ASTR 68

__global__ __launch_bounds__(256)
void attn_part(const int* __restrict__ um_p) {
    int s  = blockIdx.x;
    int h  = blockIdx.y;
    int qb = blockIdx.z;
    int um = *um_p;
    bool masked = (um != 0) && (qb < B_X);
    if (masked && s >= 5) return;   // whole block exits before any barrier
    int kbase = masked ? (qb * KV_PER_B + s * 64) : (s * 64);

    extern __shared__ float smf[];
    float* Qs = smf;                    // [d][q] pre-scaled
    float* Ks = smf + 64 * ASTR;        // [d][k]
    float* Vs = smf + 2 * 64 * ASTR;    // [k][d]
    float* Ps = smf + 3 * 64 * ASTR;    // [q][k]
    float* mrow = smf + 4 * 64 * ASTR;  // [64]
    float* lrow = mrow + 64;

    int tid = threadIdx.x;
    int ty = tid >> 4, tx = tid & 15;

    #pragma unroll
    for (int it = 0; it < 4; it++) {
        int row = ty + it * 16;
        int col = tx * 4;
        float4 v = *(const float4*)&g_q[(size_t)(qb * 64 + row) * DD + h * DH + col];
        Qs[(col + 0) * ASTR + row] = v.x * 0.125f;
        Qs[(col + 1) * ASTR + row] = v.y * 0.125f;
        Qs[(col + 2) * ASTR + row] = v.z * 0.125f;
        Qs[(col + 3) * ASTR + row] = v.w * 0.125f;
        const float* base = g_kv + (size_t)(kbase + row) * (2 * DD) + h * DH + col;
        float4 kk = *(const float4*)base;
        Ks[(col + 0) * ASTR + row] = kk.x;
        Ks[(col + 1) * ASTR + row] = kk.y;
        Ks[(col + 2) * ASTR + row] = kk.z;
        Ks[(col + 3) * ASTR + row] = kk.w;
        *(float4*)&Vs[row * ASTR + col] = *(const float4*)(base + DD);
    }
    __syncthreads();

    float sacc[4][4] = {};
    #pragma unroll
    for (int d = 0; d < 64; d++) {
        float4 aq = *(const float4*)&Qs[d * ASTR + ty * 4];
        float4 bk = *(const float4*)&Ks[d * ASTR + tx * 4];
        sacc[0][0] += aq.x * bk.x; sacc[0][1] += aq.x * bk.y;
        sacc[0][2] += aq.x * bk.z; sacc[0][3] += aq.x * bk.w;
        sacc[1][0] += aq.y * bk.x; sacc[1][1] += aq.y * bk.y;
        sacc[1][2] += aq.y * bk.z; sacc[1][3] += aq.y * bk.w;
        sacc[2][0] += aq.z * bk.x; sacc[2][1] += aq.z * bk.y;
        sacc[2][2] += aq.z * bk.z; sacc[2][3] += aq.z * bk.w;
        sacc[3][0] += aq.w * bk.x; sacc[3][1] += aq.w * bk.y;
        sacc[3][2] += aq.w * bk.z; sacc[3][3] += aq.w * bk.w;
    }
    #pragma unroll
    for (int i = 0; i < 4; i++)
        #pragma unroll
        for (int j = 0; j < 4; j++)
            Ps[(ty * 4 + i) * ASTR + tx * 4 + j] = sacc[i][j];
    __syncthreads();

    {
        int r = tid >> 2, part = tid & 3;
        float rm = -INFINITY;
        #pragma unroll
        for (int i = 0; i < 16; i++)
            rm = fmaxf(rm, Ps[r * ASTR + part * 16 + i]);
        rm = fmaxf(rm, __shfl_xor_sync(0xFFFFFFFFu, rm, 1));
        rm = fmaxf(rm, __shfl_xor_sync(0xFFFFFFFFu, rm, 2));
        float psum = 0.f;
        #pragma unroll
        for (int i = 0; i < 16; i++) {
            float p = __expf(Ps[r * ASTR + part * 16 + i] - rm);
            Ps[r * ASTR + part * 16 + i] = p;
            psum += p;
        }
        psum += __shfl_xor_sync(0xFFFFFFFFu, psum, 1);
        psum += __shfl_xor_sync(0xFFFFFFFFu, psum, 2);
        if (part == 0) { mrow[r] = rm; lrow[r] = psum; }
    }
    __syncthreads();

    float oacc[4][4] = {};
    #pragma unroll
    for (int k = 0; k < 64; k++) {
        float4 v4 = *(const float4*)&Vs[k * ASTR + tx * 4];
        float p0 = Ps[(ty * 4 + 0) * ASTR + k];
        float p1 = Ps[(ty * 4 + 1) * ASTR + k];
        float p2 = Ps[(ty * 4 + 2) * ASTR + k];
        float p3 = Ps[(ty * 4 + 3) * ASTR + k];
        oacc[0][0] += p0 * v4.x; oacc[0][1] += p0 * v4.y;
        oacc[0][2] += p0 * v4.z; oacc[0][3] += p0 * v4.w;
        oacc[1][0] += p1 * v4.x; oacc[1][1] += p1 * v4.y;
        oacc[1][2] += p1 * v4.z; oacc[1][3] += p1 * v4.w;
        oacc[2][0] += p2 * v4.x; oacc[2][1] += p2 * v4.y;
        oacc[2][2] += p2 * v4.z; oacc[2][3] += p2 * v4.w;
        oacc[3][0] += p3 * v4.x; oacc[3][1] += p3 * v4.y;
        oacc[3][2] += p3 * v4.z; oacc[3][3] += p3 * v4.w;
    }

    int pidx = (qb * HEADS + h) * NSUB + s;
    #pragma unroll
    for (int i = 0; i < 4; i++) {
        float4 o = make_float4(oacc[i][0], oacc[i][1], oacc[i][2], oacc[i][3]);
        *(float4*)&g_pO[((size_t)pidx * 64 + ty * 4 + i) * 64 + tx * 4] = o;
    }
    if (tid < 64) {
        g_pm[pidx * 64 + tid] = mrow[tid];
        g_pl[pidx * 64 + tid] = lrow[tid];
    }
}

// merge partials: one block per (q,h); 4 chunk-stripes x 64 d; deterministic smem reduce
__global__ __launch_bounds__(256)
void attn_combine(const int* __restrict__ um_p) {
    int q = blockIdx.x, h = blockIdx.y;
    int qb = q >> 6, qq = q & 63;
    int um = *um_p;
    bool masked = (um != 0) && (qb < B_X);
    int ns = masked ? 5 : NSUB;
    int stripe = threadIdx.x >> 6, d = threadIdx.x & 63;
    int pbase = (qb * HEADS + h) * NSUB;

    __shared__ float sM[4], sL[4], sO[4][64];

    float lm = -INFINITY;
    for (int c = stripe; c < ns; c += 4)
        lm = fmaxf(lm, g_pm[(pbase + c) * 64 + qq]);
    if (d == 0) sM[stripe] = lm;
    __syncthreads();
    float M = fmaxf(fmaxf(sM[0], sM[1]), fmaxf(sM[2], sM[3]));

    float L = 0.f, o = 0.f;
    for (int c = stripe; c < ns; c += 4) {
        float e = __expf(g_pm[(pbase + c) * 64 + qq] - M);
        L += g_pl[(pbase + c) * 64 + qq] * e;
        o += g_pO[((size_t)(pbase + c) * 64 + qq) * 64 + d] * e;
    }
    sO[stripe][d] = o;
    if (d == 0) sL[stripe] = L;
    __syncthreads();
    if (stripe == 0) {
        float Lt = sL[0] + sL[1] + sL[2] + sL[3];
        float ot = sO[0][d] + sO[1][d] + sO[2][d] + sO[3][d];
        float r = ot / Lt;
        __nv_bfloat16 hh = __float2bfloat16(r);
        __nv_bfloat16 ll = __float2bfloat16(r - __bfloat162float(hh));
        __nv_bfloat16* dst = g_a3small + (size_t)q * K3 + h * DH + d;
        dst[0] = hh; dst[2048] = ll;
    }
}

// ---------------- launch ----------------
#define ATTN_SMEM ((4 * 64 * ASTR + 192) * (int)sizeof(float))   /* 70400 B */

extern "C" void kernel_launch(void* const* d_in, const int* in_sizes, int n_in,
                              void* d_out, int out_size) {
    const float* x    = (const float*)d_in[0];
    const float* lat  = (const float*)d_in[1];
    const float* g1   = (const float*)d_in[2];
    const float* b1   = (const float*)d_in[3];
    const float* g2   = (const float*)d_in[4];
    const float* b2   = (const float*)d_in[5];
    const float* Wq   = (const float*)d_in[6];
    const float* Wkv  = (const float*)d_in[7];
    const float* Wout = (const float*)d_in[8];
    const int*   um   = (const int*)d_in[9];
    float* out = (float*)d_out;

    cudaFuncSetAttribute(gemm_qkv,  cudaFuncAttributeMaxDynamicSharedMemorySize, GEMM3_SMEM);
    cudaFuncSetAttribute(gemm_out,  cudaFuncAttributeMaxDynamicSharedMemorySize, GEMM3_64_SMEM);
    cudaFuncSetAttribute(attn_part, cudaFuncAttributeMaxDynamicSharedMemorySize, ATTN_SMEM);

    // 1. LayerNorm + all weight conversions in ONE launch (no duplicate segments)
    ln_convW<<<LN_BLKS + 4096, 256>>>(x, lat, g1, b1, g2, b2, Wq, Wkv, Wout);

    // 2. Q + KV projections (redundancy-free chunk loads, 360 CTAs)
    gemm_qkv<<<KV_TILES + Q_TILES, 256, GEMM3_SMEM>>>();

    // 3. attention partials + 4-way-parallel combine
    attn_part<<<dim3(NSUB, HEADS, B_LAT), 256, ATTN_SMEM>>>(um);
    attn_combine<<<dim3(ROWS_LAT, HEADS), 256>>>(um);

    // 4. output projection (redundancy-free 64-row tiles, 72 CTAs)
    gemm_out<<<dim3(DD / 128, ROWS_LAT / 64), 256, GEMM3_64_SMEM>>>(out);
}